// round 2
// baseline (speedup 1.0000x reference)
#include <cuda_runtime.h>
#include <math.h>

#define NA 48
#define NB 24
#define DIM 286
#define NBATCH 256
#define NMU 6
#define L5OFF 165

// Scratch (static device globals; no allocation)
__device__ float g_c[NA * NMU];          // cos-like per (x, mu)
__device__ float g_s[NA * NMU];          // sin-like per (x, mu)
__device__ float g_act;                  // normalize2mom constant for tanh
__device__ float g_part[1024];           // partials for the activation integral
__device__ float g_Q[NBATCH * 36 * 4 * NB];  // per-(b,y) Q forms [b][36][4][y]

__constant__ int c_off[6] = {0, 1, 10, 35, 84, 165};

// ---------------------------------------------------------------------------
// Replicate reference ACT_CST = (trapz over 1e6+1 pts of tanh(x)^2 * N(0,1))^-1/2
// ---------------------------------------------------------------------------
__global__ void act_kernel() {
    int tid = blockIdx.x * blockDim.x + threadIdx.x;  // 1024*256 = 262144
    float sum = 0.f;
    for (int i = tid; i <= 1000000; i += 262144) {
        float x = -12.f + (float)i * 2.4e-5f;
        float t = tanhf(x);
        float p = __expf(-0.5f * x * x);
        sum += t * t * p;
    }
    for (int o = 16; o; o >>= 1) sum += __shfl_down_sync(0xffffffffu, sum, o);
    __shared__ float ws[8];
    int w = threadIdx.x >> 5;
    if ((threadIdx.x & 31) == 0) ws[w] = sum;
    __syncthreads();
    if (threadIdx.x == 0) {
        float b = 0.f;
        for (int i = 0; i < 8; i++) b += ws[i];
        g_part[blockIdx.x] = b;
    }
}

// ---------------------------------------------------------------------------
// Prep: per-sector 2x2 alpha-rotation (c,s) from the l=5 block of D:
// Ra5[x] = D5[x,0,0] * D5[0,0,0]^T / 11  (Rb orthogonal, Ra(0)=I)
// ---------------------------------------------------------------------------
__global__ void prep_kernel(const float* __restrict__ D) {
    int t = threadIdx.x;
    if (t < NA * NMU) {
        int x = t / NMU, mu = t % NMU;
        int p0 = 5 - mu, p1 = 5 + mu;
        const float* X = D + (size_t)x * NB * NA * DIM + L5OFF;
        const float* Z = D + L5OFF;
        float a00 = 0.f, a01 = 0.f, a10 = 0.f, a11 = 0.f;
        for (int k = 0; k < 11; k++) {
            float xp0 = X[p0 * 11 + k], xp1 = X[p1 * 11 + k];
            float zp0 = Z[p0 * 11 + k], zp1 = Z[p1 * 11 + k];
            a00 += xp0 * zp0; a01 += xp0 * zp1;
            a10 += xp1 * zp0; a11 += xp1 * zp1;
        }
        const float inv11 = 1.f / 11.f;
        g_c[t] = 0.5f * (a00 + a11) * inv11;
        g_s[t] = 0.5f * (a01 - a10) * inv11;
    }
    if (t == 0) {
        float tot = 0.f;
        for (int i = 0; i < 1024; i++) tot += g_part[i];
        float I = tot * 2.4e-5f * 0.3989422804014327f;
        g_act = 1.0f / sqrtf(I);
    }
}

// ---------------------------------------------------------------------------
// Main: one CTA per (batch b, beta index y). Produces Q forms into g_Q.
// ---------------------------------------------------------------------------
__global__ __launch_bounds__(256) void so3_main(const float* __restrict__ feat,
                                                const float* __restrict__ D,
                                                const float* __restrict__ qw) {
    const int b = blockIdx.x / NB;
    const int y = blockIdx.x % NB;
    const int t = threadIdx.x;

    __shared__ float sF[DIM];
    __shared__ float sB[DIM];
    __shared__ float4 strig4[NA * 3];      // [x]: (c0,s0,c1,s1)(c2,s2,c3,s3)(c4,s4,c5,s5)
    __shared__ float4 sP4[36];             // (P00,P01,P10,P11)
    __shared__ float2 sT2[NMU][NA];        // (t0,t1)
    __shared__ float sG[NA][NA + 1];
    __shared__ float2 sU2[NMU][NA + 1];    // (u0,u1)

    float* strig = (float*)strig4;

    for (int i = t; i < DIM; i += 256) {
        sF[i] = feat[b * DIM + i];
        sB[i] = D[(size_t)y * NA * DIM + i];  // D[0][y][0][i]
    }
    for (int i = t; i < NA * NMU; i += 256) {
        int x = i / NMU, mu = i % NMU;
        strig[x * 12 + mu * 2 + 0] = g_c[i];
        strig[x * 12 + mu * 2 + 1] = g_s[i];
    }
    __syncthreads();

    // --- P forms -----------------------------------------------------------
    if (t < 36) {
        int mu = t / 6, nu = t % 6;
        float P00 = 0.f, P01 = 0.f, P10 = 0.f, P11 = 0.f;
        int l0 = mu > nu ? mu : nu;
        for (int l = l0; l <= 5; l++) {
            int dl = 2 * l + 1, off = c_off[l];
            int r0 = l - mu, r1 = l + mu, q0 = l - nu, q1 = l + nu;
            float F00 = sF[off + r0 * dl + q0], F01 = sF[off + r0 * dl + q1];
            float F10 = sF[off + r1 * dl + q0], F11 = sF[off + r1 * dl + q1];
            float B00 = sB[off + r0 * dl + q0], B01 = sB[off + r0 * dl + q1];
            float B10 = sB[off + r1 * dl + q0], B11 = sB[off + r1 * dl + q1];
            if (mu == 0) { F10 = F11 = 0.f; B10 = B11 = 0.f; }
            if (nu == 0) { F01 = F11 = 0.f; B01 = B11 = 0.f; }
            P00 +=  F00 * B00 + F01 * B01 + F10 * B10 + F11 * B11;
            P01 += -F00 * B01 + F01 * B00 - F10 * B11 + F11 * B10;
            P10 +=  F00 * B10 + F01 * B11 - F10 * B00 - F11 * B01;
            P11 += -F00 * B11 + F01 * B10 + F10 * B01 - F11 * B00;
        }
        sP4[t] = make_float4(P00, P01, P10, P11);
    }
    __syncthreads();

    // --- T stage: contract nu with z-trig ---------------------------------
    for (int i = t; i < NMU * NA; i += 256) {
        int mu = i / NA, z = i % NA;
        float t0 = 0.f, t1 = 0.f;
#pragma unroll
        for (int nu = 0; nu < NMU; nu++) {
            float4 P = sP4[mu * 6 + nu];
            float2 cs = *(const float2*)(strig + z * 12 + nu * 2);
            t0 += P.x * cs.x + P.y * cs.y;
            t1 += P.z * cs.x + P.w * cs.y;
        }
        sT2[mu][z] = make_float2(t0, t1);
    }
    __syncthreads();

    // --- synthesis + activation (register-tiled 3x3 outer product) --------
    {
        const float inv_s = 1.f / sqrtf(286.f);
        const float actq = g_act * qw[y];
        int xt = t >> 4, zt = t & 15;
        int x0 = xt * 3, z0 = zt * 3;
        float a00 = 0.f, a01 = 0.f, a02 = 0.f;
        float a10 = 0.f, a11 = 0.f, a12 = 0.f;
        float a20 = 0.f, a21 = 0.f, a22 = 0.f;
#pragma unroll
        for (int mu = 0; mu < NMU; mu++) {
            float2 c0 = *(const float2*)(strig + (x0 + 0) * 12 + mu * 2);
            float2 c1 = *(const float2*)(strig + (x0 + 1) * 12 + mu * 2);
            float2 c2 = *(const float2*)(strig + (x0 + 2) * 12 + mu * 2);
            float2 T0 = sT2[mu][z0 + 0];
            float2 T1 = sT2[mu][z0 + 1];
            float2 T2 = sT2[mu][z0 + 2];
            a00 += c0.x * T0.x + c0.y * T0.y;
            a01 += c0.x * T1.x + c0.y * T1.y;
            a02 += c0.x * T2.x + c0.y * T2.y;
            a10 += c1.x * T0.x + c1.y * T0.y;
            a11 += c1.x * T1.x + c1.y * T1.y;
            a12 += c1.x * T2.x + c1.y * T2.y;
            a20 += c2.x * T0.x + c2.y * T0.y;
            a21 += c2.x * T1.x + c2.y * T1.y;
            a22 += c2.x * T2.x + c2.y * T2.y;
        }
        sG[x0 + 0][z0 + 0] = actq * tanhf(a00 * inv_s);
        sG[x0 + 0][z0 + 1] = actq * tanhf(a01 * inv_s);
        sG[x0 + 0][z0 + 2] = actq * tanhf(a02 * inv_s);
        sG[x0 + 1][z0 + 0] = actq * tanhf(a10 * inv_s);
        sG[x0 + 1][z0 + 1] = actq * tanhf(a11 * inv_s);
        sG[x0 + 1][z0 + 2] = actq * tanhf(a12 * inv_s);
        sG[x0 + 2][z0 + 0] = actq * tanhf(a20 * inv_s);
        sG[x0 + 2][z0 + 1] = actq * tanhf(a21 * inv_s);
        sG[x0 + 2][z0 + 2] = actq * tanhf(a22 * inv_s);
    }
    __syncthreads();

    // --- U stage: contract x with trig; 4 lanes split x, shuffle-reduce ---
    if (t < 192) {
        int z = t >> 2, xg = t & 3;
        float u0 = 0.f, u1 = 0.f, u2 = 0.f, u3 = 0.f, u4 = 0.f, u5 = 0.f;
        float u6 = 0.f, u7 = 0.f, u8 = 0.f, u9 = 0.f, u10 = 0.f, u11 = 0.f;
#pragma unroll
        for (int k = 0; k < 12; k++) {
            int x = xg * 12 + k;
            float g = sG[x][z];
            float4 ta = strig4[x * 3 + 0];
            float4 tb = strig4[x * 3 + 1];
            float4 tc = strig4[x * 3 + 2];
            u0 += ta.x * g;  u1 += ta.y * g;  u2 += ta.z * g;  u3 += ta.w * g;
            u4 += tb.x * g;  u5 += tb.y * g;  u6 += tb.z * g;  u7 += tb.w * g;
            u8 += tc.x * g;  u9 += tc.y * g;  u10 += tc.z * g; u11 += tc.w * g;
        }
#define RED(v) v += __shfl_xor_sync(0xffffffffu, v, 1); v += __shfl_xor_sync(0xffffffffu, v, 2)
        RED(u0); RED(u1); RED(u2); RED(u3); RED(u4); RED(u5);
        RED(u6); RED(u7); RED(u8); RED(u9); RED(u10); RED(u11);
#undef RED
        if (xg == 0) {
            sU2[0][z] = make_float2(u0, u1);
            sU2[1][z] = make_float2(u2, u3);
            sU2[2][z] = make_float2(u4, u5);
            sU2[3][z] = make_float2(u6, u7);
            sU2[4][z] = make_float2(u8, u9);
            sU2[5][z] = make_float2(u10, u11);
        }
    }
    __syncthreads();

    // --- Q forms + store to global ----------------------------------------
    if (t < 36) {
        int mu = t / 6, nu = t % 6;
        float Q00 = 0.f, Q01 = 0.f, Q10 = 0.f, Q11 = 0.f;
        for (int z = 0; z < NA; z++) {
            float2 u = sU2[mu][z];
            float2 cs = *(const float2*)(strig + z * 12 + nu * 2);
            Q00 += u.x * cs.x; Q01 += u.x * cs.y;
            Q10 += u.y * cs.x; Q11 += u.y * cs.y;
        }
        int base = ((b * 36 + t) * 4) * NB + y;
        g_Q[base + 0 * NB] = Q00;
        g_Q[base + 1 * NB] = Q01;
        g_Q[base + 2 * NB] = Q10;
        g_Q[base + 3 * NB] = Q11;
    }
}

// ---------------------------------------------------------------------------
// Scatter: grid (91 tasks, 256 b), 32 threads. Task = (l, mu<=l, nu<=l).
// Sums 24 y-contributions via warp shuffle; each output written exactly once.
// ---------------------------------------------------------------------------
__global__ void scatter_kernel(const float* __restrict__ D, float* __restrict__ out) {
    int task = blockIdx.x;   // 0..90
    int b    = blockIdx.y;   // 0..255
    int l = 0, rem = task;
    while (rem >= (l + 1) * (l + 1)) { rem -= (l + 1) * (l + 1); l++; }
    int mu = rem / (l + 1), nu = rem % (l + 1);

    int y = threadIdx.x;     // lanes 0..31; 24 active
    int dl = 2 * l + 1, off = c_off[l];
    int r0 = l - mu, r1 = l + mu, q0 = l - nu, q1 = l + nu;

    float o00 = 0.f, o01 = 0.f, o10 = 0.f, o11 = 0.f;
    if (y < NB) {
        int qb = ((b * 36 + mu * 6 + nu) * 4) * NB + y;
        float Q00 = g_Q[qb + 0 * NB], Q01 = g_Q[qb + 1 * NB];
        float Q10 = g_Q[qb + 2 * NB], Q11 = g_Q[qb + 3 * NB];
        const float* By = D + (size_t)y * NA * DIM;
        float B00 = By[off + r0 * dl + q0], B01 = By[off + r0 * dl + q1];
        float B10 = By[off + r1 * dl + q0], B11 = By[off + r1 * dl + q1];
        if (mu == 0) { B10 = B11 = 0.f; }
        if (nu == 0) { B01 = B11 = 0.f; }
        o00 =  Q00 * B00 - Q01 * B01 + Q10 * B10 - Q11 * B11;
        o01 =  Q00 * B01 + Q01 * B00 + Q10 * B11 + Q11 * B10;
        o10 =  Q00 * B10 - Q01 * B11 - Q10 * B00 + Q11 * B01;
        o11 =  Q00 * B11 + Q01 * B10 - Q10 * B01 - Q11 * B00;
    }
#pragma unroll
    for (int o = 16; o; o >>= 1) {
        o00 += __shfl_down_sync(0xffffffffu, o00, o);
        o01 += __shfl_down_sync(0xffffffffu, o01, o);
        o10 += __shfl_down_sync(0xffffffffu, o10, o);
        o11 += __shfl_down_sync(0xffffffffu, o11, o);
    }
    if (threadIdx.x == 0) {
        const float ss = sqrtf(286.f);
        float* ob = out + (size_t)b * DIM + off;
        ob[r0 * dl + q0] = ss * o00;
        if (nu > 0) ob[r0 * dl + q1] = ss * o01;
        if (mu > 0) ob[r1 * dl + q0] = ss * o10;
        if (mu > 0 && nu > 0) ob[r1 * dl + q1] = ss * o11;
    }
}

extern "C" void kernel_launch(void* const* d_in, const int* in_sizes, int n_in,
                              void* d_out, int out_size) {
    const float* feat = (const float*)d_in[0];  // [256, 286]
    const float* D    = (const float*)d_in[1];  // [48, 24, 48, 286]
    const float* qw   = (const float*)d_in[2];  // [24]
    float* out        = (float*)d_out;          // [256, 286]

    act_kernel<<<1024, 256>>>();
    prep_kernel<<<1, 512>>>(D);
    so3_main<<<NBATCH * NB, 256>>>(feat, D, qw);
    scatter_kernel<<<dim3(91, NBATCH), 32>>>(D, out);
}

// round 3
// speedup vs baseline: 1.1729x; 1.1729x over previous
#include <cuda_runtime.h>
#include <math.h>

#define NA 48
#define NB 24
#define DIM 286
#define NBATCH 256
#define NMU 6
#define L5OFF 165

// Scratch (static device globals; no allocation)
__device__ float g_c[NA * NMU];                // cos-like per (x, mu)
__device__ float g_s[NA * NMU];                // sin-like per (x, mu)
__device__ float g_act;                        // normalize2mom constant for tanh
__device__ float g_part[48];                   // partials for activation integral
__device__ float g_Q[NBATCH * NB * 144];       // per-(b,y) Q forms [b][y][36*4]

__constant__ int c_off[6] = {0, 1, 10, 35, 84, 165};

// fast exact-enough tanh: 1 - 2/(e^{2x}+1)   (rel err ~1e-6, robust at +-inf)
__device__ __forceinline__ float ftanh(float x) {
    float e = __expf(2.0f * x);
    return 1.0f - 2.0f / (e + 1.0f);
}

// ---------------------------------------------------------------------------
// ACT_CST integral: trapz of tanh(x)^2 * N(0,1) over [-12,12], 100001 pts
// (quadrature error ~5e-9 vs reference's 1e6-pt trapz; endpoints ~1e-32)
// ---------------------------------------------------------------------------
__global__ void act_kernel() {
    int tid = blockIdx.x * blockDim.x + threadIdx.x;  // 48*256 = 12288
    float sum = 0.f;
    for (int i = tid; i <= 100000; i += 12288) {
        float x = -12.f + (float)i * 2.4e-4f;
        float t = tanhf(x);
        float p = __expf(-0.5f * x * x);
        sum += t * t * p;
    }
    for (int o = 16; o; o >>= 1) sum += __shfl_down_sync(0xffffffffu, sum, o);
    __shared__ float ws[8];
    int w = threadIdx.x >> 5;
    if ((threadIdx.x & 31) == 0) ws[w] = sum;
    __syncthreads();
    if (threadIdx.x == 0) {
        float b = 0.f;
        for (int i = 0; i < 8; i++) b += ws[i];
        g_part[blockIdx.x] = b;
    }
}

// ---------------------------------------------------------------------------
// Prep: per-sector 2x2 alpha-rotation (c,s) from the l=5 block of D:
// Ra5[x] = D5[x,0,0] * D5[0,0,0]^T / 11  (Rb orthogonal, Ra(0)=I)
// ---------------------------------------------------------------------------
__global__ void prep_kernel(const float* __restrict__ D) {
    int t = threadIdx.x;
    if (t < NA * NMU) {
        int x = t / NMU, mu = t % NMU;
        int p0 = 5 - mu, p1 = 5 + mu;
        const float* X = D + (size_t)x * NB * NA * DIM + L5OFF;
        const float* Z = D + L5OFF;
        float a00 = 0.f, a01 = 0.f, a10 = 0.f, a11 = 0.f;
        for (int k = 0; k < 11; k++) {
            float xp0 = X[p0 * 11 + k], xp1 = X[p1 * 11 + k];
            float zp0 = Z[p0 * 11 + k], zp1 = Z[p1 * 11 + k];
            a00 += xp0 * zp0; a01 += xp0 * zp1;
            a10 += xp1 * zp0; a11 += xp1 * zp1;
        }
        const float inv11 = 1.f / 11.f;
        g_c[t] = 0.5f * (a00 + a11) * inv11;
        g_s[t] = 0.5f * (a01 - a10) * inv11;
    }
    if (t == 0) {
        float tot = 0.f;
        for (int i = 0; i < 48; i++) tot += g_part[i];
        float I = tot * 2.4e-4f * 0.3989422804014327f;
        g_act = 1.0f / sqrtf(I);
    }
}

// ---------------------------------------------------------------------------
// Main: one CTA per (batch b, beta index y). Produces Q forms into g_Q.
// ---------------------------------------------------------------------------
__global__ __launch_bounds__(256) void so3_main(const float* __restrict__ feat,
                                                const float* __restrict__ D,
                                                const float* __restrict__ qw) {
    const int b = blockIdx.x / NB;
    const int y = blockIdx.x % NB;
    const int t = threadIdx.x;

    __shared__ float sF[DIM];
    __shared__ float sB[DIM];
    __shared__ float4 strig4[NA * 3];      // [x]: (c0,s0,c1,s1)(c2,s2,c3,s3)(c4,s4,c5,s5)
    __shared__ float2 strigT[NMU][NA];     // transposed copy: [nu][z] -> (c,s)
    __shared__ float4 sP4[36];             // (P00,P01,P10,P11)
    __shared__ float2 sT2[NMU][NA];        // (t0,t1)
    __shared__ float sG[NA][NA + 1];
    __shared__ float2 sU2[NMU][NA + 1];    // (u0,u1)

    float* strig = (float*)strig4;

    for (int i = t; i < DIM; i += 256) {
        sF[i] = feat[b * DIM + i];
        sB[i] = D[(size_t)y * NA * DIM + i];  // D[0][y][0][i]
    }
    for (int i = t; i < NA * NMU; i += 256) {
        int x = i / NMU, mu = i % NMU;
        float c = g_c[i], s = g_s[i];
        strig[x * 12 + mu * 2 + 0] = c;
        strig[x * 12 + mu * 2 + 1] = s;
        strigT[mu][x] = make_float2(c, s);
    }
    __syncthreads();

    // --- P forms -----------------------------------------------------------
    if (t < 36) {
        int mu = t / 6, nu = t % 6;
        float P00 = 0.f, P01 = 0.f, P10 = 0.f, P11 = 0.f;
        int l0 = mu > nu ? mu : nu;
        for (int l = l0; l <= 5; l++) {
            int dl = 2 * l + 1, off = c_off[l];
            int r0 = l - mu, r1 = l + mu, q0 = l - nu, q1 = l + nu;
            float F00 = sF[off + r0 * dl + q0], F01 = sF[off + r0 * dl + q1];
            float F10 = sF[off + r1 * dl + q0], F11 = sF[off + r1 * dl + q1];
            float B00 = sB[off + r0 * dl + q0], B01 = sB[off + r0 * dl + q1];
            float B10 = sB[off + r1 * dl + q0], B11 = sB[off + r1 * dl + q1];
            if (mu == 0) { F10 = F11 = 0.f; B10 = B11 = 0.f; }
            if (nu == 0) { F01 = F11 = 0.f; B01 = B11 = 0.f; }
            P00 +=  F00 * B00 + F01 * B01 + F10 * B10 + F11 * B11;
            P01 += -F00 * B01 + F01 * B00 - F10 * B11 + F11 * B10;
            P10 +=  F00 * B10 + F01 * B11 - F10 * B00 - F11 * B01;
            P11 += -F00 * B11 + F01 * B10 + F10 * B01 - F11 * B00;
        }
        sP4[t] = make_float4(P00, P01, P10, P11);
    }
    __syncthreads();

    // --- T stage: contract nu with z-trig (conflict-free via strigT) ------
    for (int i = t; i < NMU * NA; i += 256) {
        int mu = i / NA, z = i % NA;
        float t0 = 0.f, t1 = 0.f;
#pragma unroll
        for (int nu = 0; nu < NMU; nu++) {
            float4 P = sP4[mu * 6 + nu];
            float2 cs = strigT[nu][z];
            t0 += P.x * cs.x + P.y * cs.y;
            t1 += P.z * cs.x + P.w * cs.y;
        }
        sT2[mu][z] = make_float2(t0, t1);
    }
    __syncthreads();

    // --- synthesis + activation (register-tiled 3x3 outer product) --------
    {
        const float inv_s = 1.f / sqrtf(286.f);
        const float actq = g_act * qw[y];
        int xt = t >> 4, zt = t & 15;
        int x0 = xt * 3, z0 = zt * 3;
        float a00 = 0.f, a01 = 0.f, a02 = 0.f;
        float a10 = 0.f, a11 = 0.f, a12 = 0.f;
        float a20 = 0.f, a21 = 0.f, a22 = 0.f;
#pragma unroll
        for (int mu = 0; mu < NMU; mu++) {
            float2 c0 = *(const float2*)(strig + (x0 + 0) * 12 + mu * 2);
            float2 c1 = *(const float2*)(strig + (x0 + 1) * 12 + mu * 2);
            float2 c2 = *(const float2*)(strig + (x0 + 2) * 12 + mu * 2);
            float2 T0 = sT2[mu][z0 + 0];
            float2 T1 = sT2[mu][z0 + 1];
            float2 T2 = sT2[mu][z0 + 2];
            a00 += c0.x * T0.x + c0.y * T0.y;
            a01 += c0.x * T1.x + c0.y * T1.y;
            a02 += c0.x * T2.x + c0.y * T2.y;
            a10 += c1.x * T0.x + c1.y * T0.y;
            a11 += c1.x * T1.x + c1.y * T1.y;
            a12 += c1.x * T2.x + c1.y * T2.y;
            a20 += c2.x * T0.x + c2.y * T0.y;
            a21 += c2.x * T1.x + c2.y * T1.y;
            a22 += c2.x * T2.x + c2.y * T2.y;
        }
        sG[x0 + 0][z0 + 0] = actq * ftanh(a00 * inv_s);
        sG[x0 + 0][z0 + 1] = actq * ftanh(a01 * inv_s);
        sG[x0 + 0][z0 + 2] = actq * ftanh(a02 * inv_s);
        sG[x0 + 1][z0 + 0] = actq * ftanh(a10 * inv_s);
        sG[x0 + 1][z0 + 1] = actq * ftanh(a11 * inv_s);
        sG[x0 + 1][z0 + 2] = actq * ftanh(a12 * inv_s);
        sG[x0 + 2][z0 + 0] = actq * ftanh(a20 * inv_s);
        sG[x0 + 2][z0 + 1] = actq * ftanh(a21 * inv_s);
        sG[x0 + 2][z0 + 2] = actq * ftanh(a22 * inv_s);
    }
    __syncthreads();

    // --- U stage: contract x with trig; 4 lanes split x, shuffle-reduce ---
    if (t < 192) {
        int z = t >> 2, xg = t & 3;
        float u0 = 0.f, u1 = 0.f, u2 = 0.f, u3 = 0.f, u4 = 0.f, u5 = 0.f;
        float u6 = 0.f, u7 = 0.f, u8 = 0.f, u9 = 0.f, u10 = 0.f, u11 = 0.f;
#pragma unroll
        for (int k = 0; k < 12; k++) {
            int x = xg * 12 + k;
            float g = sG[x][z];
            float4 ta = strig4[x * 3 + 0];
            float4 tb = strig4[x * 3 + 1];
            float4 tc = strig4[x * 3 + 2];
            u0 += ta.x * g;  u1 += ta.y * g;  u2 += ta.z * g;  u3 += ta.w * g;
            u4 += tb.x * g;  u5 += tb.y * g;  u6 += tb.z * g;  u7 += tb.w * g;
            u8 += tc.x * g;  u9 += tc.y * g;  u10 += tc.z * g; u11 += tc.w * g;
        }
#define RED(v) v += __shfl_xor_sync(0xffffffffu, v, 1); v += __shfl_xor_sync(0xffffffffu, v, 2)
        RED(u0); RED(u1); RED(u2); RED(u3); RED(u4); RED(u5);
        RED(u6); RED(u7); RED(u8); RED(u9); RED(u10); RED(u11);
#undef RED
        if (xg == 0) {
            sU2[0][z] = make_float2(u0, u1);
            sU2[1][z] = make_float2(u2, u3);
            sU2[2][z] = make_float2(u4, u5);
            sU2[3][z] = make_float2(u6, u7);
            sU2[4][z] = make_float2(u8, u9);
            sU2[5][z] = make_float2(u10, u11);
        }
    }
    __syncthreads();

    // --- Q forms + coalesced store ----------------------------------------
    if (t < 36) {
        int mu = t / 6, nu = t % 6;
        float Q00 = 0.f, Q01 = 0.f, Q10 = 0.f, Q11 = 0.f;
        for (int z = 0; z < NA; z++) {
            float2 u = sU2[mu][z];
            float2 cs = *(const float2*)(strig + z * 12 + nu * 2);
            Q00 += u.x * cs.x; Q01 += u.x * cs.y;
            Q10 += u.y * cs.x; Q11 += u.y * cs.y;
        }
        *(float4*)(g_Q + ((size_t)(b * NB + y)) * 144 + t * 4) =
            make_float4(Q00, Q01, Q10, Q11);
    }
}

// ---------------------------------------------------------------------------
// Scatter: one CTA per batch b (288 threads). Stage B-slice + Q in smem,
// each thread computes one output element, summing 24 y-contributions.
//   out(r,q) = sum_y Q00 B(r,q) + sq Q01 B(r,qb) + sr Q10 B(rb,q) + sr sq Q11 B(rb,qb)
// ---------------------------------------------------------------------------
__global__ __launch_bounds__(288) void scatter_kernel(const float* __restrict__ D,
                                                      float* __restrict__ out) {
    const int b = blockIdx.x;
    const int t = threadIdx.x;
    __shared__ float sB[NB * 287];
    __shared__ float4 sQ4[NB * 37];
    float* sQ = (float*)sQ4;

    for (int i = t; i < NB * DIM; i += 288) {
        int y = i / DIM, k = i - y * DIM;
        sB[y * 287 + k] = D[(size_t)y * NA * DIM + k];
    }
    const float* Qb = g_Q + (size_t)b * NB * 144;
    for (int i = t; i < NB * 144; i += 288) {
        int y = i / 144, k = i - y * 144;
        sQ[y * 148 + k] = Qb[i];
    }
    __syncthreads();

    if (t < DIM) {
        int l = 5;
        if (t < 165) l = 4;
        if (t < 84)  l = 3;
        if (t < 35)  l = 2;
        if (t < 10)  l = 1;
        if (t < 1)   l = 0;
        int off = c_off[l], dl = 2 * l + 1;
        int k = t - off;
        int r = k / dl, q = k - r * dl;
        int rb = 2 * l - r, qb = 2 * l - q;
        int mu = r < l ? l - r : r - l;
        int nu = q < l ? l - q : q - l;
        float sr_ = (r < l) ? 1.f : -1.f;
        float sq_ = (q > l) ? 1.f : -1.f;
        int mn = mu * 6 + nu;
        int i_rq = t;
        int i_rqb = off + r * dl + qb;
        int i_rbq = off + rb * dl + q;
        int i_rbqb = off + rb * dl + qb;

        float A0 = 0.f, A1 = 0.f, A2 = 0.f, A3 = 0.f;
#pragma unroll 4
        for (int y = 0; y < NB; y++) {
            const float* By = sB + y * 287;
            float4 Q = sQ4[y * 37 + mn];
            A0 += Q.x * By[i_rq];
            A1 += Q.y * By[i_rqb];
            A2 += Q.z * By[i_rbq];
            A3 += Q.w * By[i_rbqb];
        }
        float acc = A0 + sq_ * A1 + sr_ * (A2 + sq_ * A3);
        out[(size_t)b * DIM + t] = sqrtf(286.f) * acc;
    }
}

extern "C" void kernel_launch(void* const* d_in, const int* in_sizes, int n_in,
                              void* d_out, int out_size) {
    const float* feat = (const float*)d_in[0];  // [256, 286]
    const float* D    = (const float*)d_in[1];  // [48, 24, 48, 286]
    const float* qw   = (const float*)d_in[2];  // [24]
    float* out        = (float*)d_out;          // [256, 286]

    act_kernel<<<48, 256>>>();
    prep_kernel<<<1, 512>>>(D);
    so3_main<<<NBATCH * NB, 256>>>(feat, D, qw);
    scatter_kernel<<<NBATCH, 288>>>(D, out);
}